// round 10
// baseline (speedup 1.0000x reference)
#include <cuda_runtime.h>

#define NPIX 786432
#define KER 9
#define CIN 16
#define COUT 16
#define TPB 128

typedef unsigned long long u64;

__device__ __forceinline__ u64 pack2(float lo, float hi) {
    u64 r; asm("mov.b64 %0, {%1, %2};" : "=l"(r) : "f"(lo), "f"(hi)); return r;
}
__device__ __forceinline__ void unpack2(u64 v, float& lo, float& hi) {
    asm("mov.b64 {%0, %1}, %2;" : "=f"(lo), "=f"(hi) : "l"(v));
}
__device__ __forceinline__ void fma2(u64& d, u64 a, u64 b) {
    asm("fma.rn.f32x2 %0, %1, %2, %0;" : "+l"(d) : "l"(a), "l"(b));
}
__device__ __forceinline__ void add2(u64& d, u64 a) {
    asm("add.rn.f32x2 %0, %0, %1;" : "+l"(d) : "l"(a));
}

__global__ __launch_bounds__(TPB, 6) void healpix_conv_kernel(
    const float* __restrict__ x,      // (2, NPIX, CIN)
    const int*   __restrict__ nb,     // (NPIX, KER)
    const float* __restrict__ w,      // (COUT, KER, CIN)
    const float* __restrict__ bias,   // (COUT,)
    float*       __restrict__ y)      // (2, NPIX, COUT)
{
    // w duplicated into (w,w) f32x2 pairs, layout [k][o][c]: the 4 lanes of a
    // pixel-group read contiguous c -> conflict-free LDS.128 multi-broadcast.
    __shared__ u64 wdup[KER * COUT * CIN];

    const int tid = threadIdx.x;
    for (int i = tid; i < KER * COUT * CIN; i += TPB) {
        const int c = i & 15;
        const int o = (i >> 4) & 15;
        const int k = i >> 8;
        const float wv = w[(o * KER + k) * CIN + c];
        wdup[i] = pack2(wv, wv);
    }
    __syncthreads();

    const int lane = tid & 31;
    const int warp = tid >> 5;
    const int q = lane & 3;        // channel-quarter owned by this lane
    const int g = lane >> 2;       // pixel group (0..7)
    const int n = (blockIdx.x * (TPB / 32) + warp) * 8 + g;   // this thread's pixel

    u64 acc[COUT];
    #pragma unroll
    for (int o = 0; o < COUT; o++) acc[o] = 0ULL;

    // quarter-row base pointers for each batch
    const float* xq0 = x + q * 4;
    const float* xq1 = x + (size_t)NPIX * CIN + q * 4;

    // prefetch all 9 neighbour indices up front (breaks idx->gather chain)
    int ids[KER];
    {
        const int* nbp = nb + (size_t)n * KER;
        #pragma unroll
        for (int k = 0; k < KER; k++) ids[k] = nbp[k];
    }

    // software pipeline depth 1 on the gathered x rows: iteration k's FMA
    // block covers the L2 latency of iteration k+1's gathers.
    float4 a_cur, b_cur;
    bool v_cur;
    {
        const int id = ids[0];
        v_cur = (id < NPIX);
        const int safe = v_cur ? id : 0;
        a_cur = *(const float4*)(xq0 + (size_t)safe * CIN);
        b_cur = *(const float4*)(xq1 + (size_t)safe * CIN);
    }

    #pragma unroll 1
    for (int k = 0; k < KER; k++) {
        // issue next iteration's gathers first (independent of everything below)
        float4 a_n, b_n;
        bool v_n = false;
        if (k + 1 < KER) {
            const int id = ids[k + 1];
            v_n = (id < NPIX);
            const int safe = v_n ? id : 0;
            a_n = *(const float4*)(xq0 + (size_t)safe * CIN);
            b_n = *(const float4*)(xq1 + (size_t)safe * CIN);
        }

        u64 xp[4];
        xp[0] = v_cur ? pack2(a_cur.x, b_cur.x) : 0ULL;
        xp[1] = v_cur ? pack2(a_cur.y, b_cur.y) : 0ULL;
        xp[2] = v_cur ? pack2(a_cur.z, b_cur.z) : 0ULL;
        xp[3] = v_cur ? pack2(a_cur.w, b_cur.w) : 0ULL;

        const u64* wk = wdup + k * COUT * CIN + q * 4;
        #pragma unroll
        for (int o = 0; o < COUT; o++) {
            const ulonglong2 wA = *(const ulonglong2*)(wk + o * CIN);
            const ulonglong2 wB = *(const ulonglong2*)(wk + o * CIN + 2);
            fma2(acc[o], xp[0], wA.x);
            fma2(acc[o], xp[1], wA.y);
            fma2(acc[o], xp[2], wB.x);
            fma2(acc[o], xp[3], wB.y);
        }

        a_cur = a_n; b_cur = b_n; v_cur = v_n;
    }

    // all-reduce partial sums across the 4 lanes of each pixel group
    #pragma unroll
    for (int o = 0; o < COUT; o++) {
        u64 t = __shfl_xor_sync(0xffffffffu, acc[o], 1);
        add2(acc[o], t);
        t = __shfl_xor_sync(0xffffffffu, acc[o], 2);
        add2(acc[o], t);
    }

    // lane q stores output channels [4q, 4q+4) for its pixel, both batches
    const float4 b4 = *(const float4*)(bias + q * 4);
    float lo0, hi0, lo1, hi1, lo2, hi2, lo3, hi3;
    unpack2(acc[q * 4 + 0], lo0, hi0);
    unpack2(acc[q * 4 + 1], lo1, hi1);
    unpack2(acc[q * 4 + 2], lo2, hi2);
    unpack2(acc[q * 4 + 3], lo3, hi3);
    float4 y0 = make_float4(lo0 + b4.x, lo1 + b4.y, lo2 + b4.z, lo3 + b4.w);
    float4 y1 = make_float4(hi0 + b4.x, hi1 + b4.y, hi2 + b4.z, hi3 + b4.w);
    *(float4*)(y + (size_t)n * COUT + q * 4) = y0;
    *(float4*)(y + (size_t)NPIX * COUT + (size_t)n * COUT + q * 4) = y1;
}

extern "C" void kernel_launch(void* const* d_in, const int* in_sizes, int n_in,
                              void* d_out, int out_size) {
    const float* x    = (const float*)d_in[0];
    const int*   nb   = (const int*)d_in[1];
    const float* w    = (const float*)d_in[2];
    const float* bias = (const float*)d_in[3];
    float*       y    = (float*)d_out;

    // 128 threads = 4 warps = 32 pixels per block
    const int blocks = NPIX / 32;   // 24576
    healpix_conv_kernel<<<blocks, TPB>>>(x, nb, w, bias, y);
}

// round 14
// speedup vs baseline: 1.4077x; 1.4077x over previous
#include <cuda_runtime.h>

#define NPIX 786432
#define KER 9
#define CIN 16
#define COUT 16
#define TPB 128

typedef unsigned long long u64;

__device__ __forceinline__ u64 pack2(float lo, float hi) {
    u64 r; asm("mov.b64 %0, {%1, %2};" : "=l"(r) : "f"(lo), "f"(hi)); return r;
}
__device__ __forceinline__ void unpack2(u64 v, float& lo, float& hi) {
    asm("mov.b64 {%0, %1}, %2;" : "=f"(lo), "=f"(hi) : "l"(v));
}
__device__ __forceinline__ void fma2(u64& d, u64 a, u64 b) {
    asm("fma.rn.f32x2 %0, %1, %2, %0;" : "+l"(d) : "l"(a), "l"(b));
}
__device__ __forceinline__ void add2(u64& d, u64 a) {
    asm("add.rn.f32x2 %0, %0, %1;" : "+l"(d) : "l"(a));
}

__global__ __launch_bounds__(TPB, 4) void healpix_conv_kernel(
    const float* __restrict__ x,      // (2, NPIX, CIN)
    const int*   __restrict__ nb,     // (NPIX, KER)
    const float* __restrict__ w,      // (COUT, KER, CIN)
    const float* __restrict__ bias,   // (COUT,)
    float*       __restrict__ y)      // (2, NPIX, COUT)
{
    // w as SCALAR f32 in smem, layout [k][o][c] (9 KB). Lane q reads its 4
    // channels per o as one LDS.128 -> half the crossbar wavefronts of the
    // duplicated-u64 layout. Duplication to (w,w) happens in registers (ALU
    // pipe, dual-issues under the FMA pipe).
    __shared__ float ws[KER * COUT * CIN];

    const int tid = threadIdx.x;
    for (int i = tid; i < KER * COUT * CIN; i += TPB) {
        const int c = i & 15;
        const int o = (i >> 4) & 15;
        const int k = i >> 8;
        ws[i] = w[(o * KER + k) * CIN + c];
    }
    __syncthreads();

    const int lane = tid & 31;
    const int warp = tid >> 5;
    const int q = lane & 3;        // channel-quarter owned by this lane
    const int g = lane >> 2;       // pixel group (0..7)
    const int wb = (blockIdx.x * (TPB / 32) + warp) * 16;   // 16 px / warp
    const int n0 = wb + g;         // pixel 0
    const int n1 = wb + 8 + g;     // pixel 1

    u64 acc[2][COUT];              // [pixel][o], each u64 = (batch0, batch1)
    #pragma unroll
    for (int p = 0; p < 2; p++)
        #pragma unroll
        for (int o = 0; o < COUT; o++) acc[p][o] = 0ULL;

    // quarter-row base pointers for each batch
    const float* xq0 = x + q * 4;
    const float* xq1 = x + (size_t)NPIX * CIN + q * 4;

    // prefetch all neighbour indices (breaks idx->gather serial chain)
    int id0[KER], id1[KER];
    {
        const int* p0 = nb + (size_t)n0 * KER;
        const int* p1 = nb + (size_t)n1 * KER;
        #pragma unroll
        for (int k = 0; k < KER; k++) { id0[k] = __ldg(p0 + k); id1[k] = __ldg(p1 + k); }
    }

    // software pipeline depth 1 on gathered rows
    float4 a0c, b0c, a1c, b1c;
    bool v0c, v1c;
    {
        v0c = (id0[0] < NPIX);
        v1c = (id1[0] < NPIX);
        const int s0 = v0c ? id0[0] : 0;
        const int s1 = v1c ? id1[0] : 0;
        a0c = __ldg((const float4*)(xq0 + (size_t)s0 * CIN));
        b0c = __ldg((const float4*)(xq1 + (size_t)s0 * CIN));
        a1c = __ldg((const float4*)(xq0 + (size_t)s1 * CIN));
        b1c = __ldg((const float4*)(xq1 + (size_t)s1 * CIN));
    }

    #pragma unroll 1
    for (int k = 0; k < KER; k++) {
        // issue next iteration's gathers first
        float4 a0n, b0n, a1n, b1n;
        bool v0n = false, v1n = false;
        if (k + 1 < KER) {
            v0n = (id0[k + 1] < NPIX);
            v1n = (id1[k + 1] < NPIX);
            const int s0 = v0n ? id0[k + 1] : 0;
            const int s1 = v1n ? id1[k + 1] : 0;
            a0n = __ldg((const float4*)(xq0 + (size_t)s0 * CIN));
            b0n = __ldg((const float4*)(xq1 + (size_t)s0 * CIN));
            a1n = __ldg((const float4*)(xq0 + (size_t)s1 * CIN));
            b1n = __ldg((const float4*)(xq1 + (size_t)s1 * CIN));
        }

        u64 xp0[4], xp1[4];
        xp0[0] = v0c ? pack2(a0c.x, b0c.x) : 0ULL;
        xp0[1] = v0c ? pack2(a0c.y, b0c.y) : 0ULL;
        xp0[2] = v0c ? pack2(a0c.z, b0c.z) : 0ULL;
        xp0[3] = v0c ? pack2(a0c.w, b0c.w) : 0ULL;
        xp1[0] = v1c ? pack2(a1c.x, b1c.x) : 0ULL;
        xp1[1] = v1c ? pack2(a1c.y, b1c.y) : 0ULL;
        xp1[2] = v1c ? pack2(a1c.z, b1c.z) : 0ULL;
        xp1[3] = v1c ? pack2(a1c.w, b1c.w) : 0ULL;

        const float* wk = ws + k * COUT * CIN + q * 4;
        #pragma unroll
        for (int o = 0; o < COUT; o++) {
            const float4 wv = *(const float4*)(wk + o * CIN);
            const u64 w0 = pack2(wv.x, wv.x);
            const u64 w1 = pack2(wv.y, wv.y);
            const u64 w2 = pack2(wv.z, wv.z);
            const u64 w3 = pack2(wv.w, wv.w);
            fma2(acc[0][o], xp0[0], w0);
            fma2(acc[0][o], xp0[1], w1);
            fma2(acc[0][o], xp0[2], w2);
            fma2(acc[0][o], xp0[3], w3);
            fma2(acc[1][o], xp1[0], w0);
            fma2(acc[1][o], xp1[1], w1);
            fma2(acc[1][o], xp1[2], w2);
            fma2(acc[1][o], xp1[3], w3);
        }

        a0c = a0n; b0c = b0n; a1c = a1n; b1c = b1n;
        v0c = v0n; v1c = v1n;
    }

    // all-reduce partial sums across the 4 lanes of each pixel group
    #pragma unroll
    for (int p = 0; p < 2; p++) {
        #pragma unroll
        for (int o = 0; o < COUT; o++) {
            u64 t = __shfl_xor_sync(0xffffffffu, acc[p][o], 1);
            add2(acc[p][o], t);
            t = __shfl_xor_sync(0xffffffffu, acc[p][o], 2);
            add2(acc[p][o], t);
        }
    }

    // lane q stores output channels [4q, 4q+4) for its pixels, both batches
    const float4 b4 = *(const float4*)(bias + q * 4);
    #pragma unroll
    for (int p = 0; p < 2; p++) {
        const int n = (p == 0) ? n0 : n1;
        float lo0, hi0, lo1, hi1, lo2, hi2, lo3, hi3;
        unpack2(acc[p][q * 4 + 0], lo0, hi0);
        unpack2(acc[p][q * 4 + 1], lo1, hi1);
        unpack2(acc[p][q * 4 + 2], lo2, hi2);
        unpack2(acc[p][q * 4 + 3], lo3, hi3);
        float4 y0 = make_float4(lo0 + b4.x, lo1 + b4.y, lo2 + b4.z, lo3 + b4.w);
        float4 y1 = make_float4(hi0 + b4.x, hi1 + b4.y, hi2 + b4.z, hi3 + b4.w);
        *(float4*)(y + (size_t)n * COUT + q * 4) = y0;
        *(float4*)(y + (size_t)NPIX * COUT + (size_t)n * COUT + q * 4) = y1;
    }
}

extern "C" void kernel_launch(void* const* d_in, const int* in_sizes, int n_in,
                              void* d_out, int out_size) {
    const float* x    = (const float*)d_in[0];
    const int*   nb   = (const int*)d_in[1];
    const float* w    = (const float*)d_in[2];
    const float* bias = (const float*)d_in[3];
    float*       y    = (float*)d_out;

    // 128 threads = 4 warps = 64 pixels per block
    const int blocks = NPIX / 64;   // 12288
    healpix_conv_kernel<<<blocks, TPB>>>(x, nb, w, bias, y);
}